// round 1
// baseline (speedup 1.0000x reference)
#include <cuda_runtime.h>
#include <cuda_fp16.h>

// Problem constants (fixed shapes from the dataset)
#define NODES_MAX 50000
#define DDIM 256          // input feature dim
#define ADIM 128          // attention dim (q or k width)
#define QKW 256           // concat width: [q | k]

// Scratch: fp16 q|k table, one 256-half row per node (25.6 MB static)
__device__ __half g_qk[(size_t)NODES_MAX * QKW];

// ---------------------------------------------------------------------------
// Kernel 1: fused projection GEMM
//   qk[n][j] = sum_d x[n][d] * W[j][d] + b[j],  W = [Wq ; Wk], b = [bq ; bk]
//   fp32 accumulate, fp16 store.
// Classic BM=64 x BN=64 x BK=16 tile, 256 threads, 4x4 register tile/thread.
// ---------------------------------------------------------------------------
__global__ void gemm_qk_kernel(const float* __restrict__ x,
                               const float* __restrict__ Wq,
                               const float* __restrict__ bq,
                               const float* __restrict__ Wk,
                               const float* __restrict__ bk,
                               int N)
{
    __shared__ float Xs[16][64];   // [k][m]
    __shared__ float Ws[16][64];   // [k][n]

    const int tid = threadIdx.x;          // 0..255
    const int tx  = tid & 15;             // 0..15 -> n
    const int ty  = tid >> 4;             // 0..15 -> m
    const int m0  = blockIdx.x * 64;
    const int n0  = blockIdx.y * 64;

    // cooperative load mapping: each thread loads one float4 of each tile
    const int lrow = tid >> 2;            // 0..63
    const int lcol = (tid & 3) * 4;       // 0,4,8,12

    float acc[4][4] = {};

    for (int k0 = 0; k0 < DDIM; k0 += 16) {
        // --- X tile [64 m x 16 k] ---
        float4 xv = make_float4(0.f, 0.f, 0.f, 0.f);
        int gm = m0 + lrow;
        if (gm < N)
            xv = *reinterpret_cast<const float4*>(x + (size_t)gm * DDIM + k0 + lcol);
        Xs[lcol + 0][lrow] = xv.x;
        Xs[lcol + 1][lrow] = xv.y;
        Xs[lcol + 2][lrow] = xv.z;
        Xs[lcol + 3][lrow] = xv.w;

        // --- W tile [64 n x 16 k] (rows 0..127 from Wq, 128..255 from Wk) ---
        int gj = n0 + lrow;   // always < 256
        const float* wrow = (gj < ADIM) ? (Wq + (size_t)gj * DDIM)
                                        : (Wk + (size_t)(gj - ADIM) * DDIM);
        float4 wv = *reinterpret_cast<const float4*>(wrow + k0 + lcol);
        Ws[lcol + 0][lrow] = wv.x;
        Ws[lcol + 1][lrow] = wv.y;
        Ws[lcol + 2][lrow] = wv.z;
        Ws[lcol + 3][lrow] = wv.w;

        __syncthreads();

        #pragma unroll
        for (int k = 0; k < 16; k++) {
            float a[4], b[4];
            #pragma unroll
            for (int i = 0; i < 4; i++) a[i] = Xs[k][ty * 4 + i];
            #pragma unroll
            for (int j = 0; j < 4; j++) b[j] = Ws[k][tx * 4 + j];
            #pragma unroll
            for (int i = 0; i < 4; i++)
                #pragma unroll
                for (int j = 0; j < 4; j++)
                    acc[i][j] = fmaf(a[i], b[j], acc[i][j]);
        }
        __syncthreads();
    }

    // epilogue: bias + fp16 store
    #pragma unroll
    for (int i = 0; i < 4; i++) {
        int gm = m0 + ty * 4 + i;
        if (gm >= N) continue;
        #pragma unroll
        for (int j = 0; j < 4; j++) {
            int gj = n0 + tx * 4 + j;
            float bias = (gj < ADIM) ? bq[gj] : bk[gj - ADIM];
            g_qk[(size_t)gm * QKW + gj] = __float2half(acc[i][j] + bias);
        }
    }
}

// ---------------------------------------------------------------------------
// Kernel 2: per-edge symmetric attention score + fused scatter-add.
// One warp per edge. pre = (1/16) * (q_s . k_d + q_d . k_s); v = exp(pre).
//   out[N + e]            = v          (diagA1)
//   out[d0row1[2e]]      += v          (diagA0, atomic)
//   out[d0row1[2e + 1]]  += v
// Each lane covers 4 of the 128 q/k dims -> four 8B L2-hit loads per lane.
// ---------------------------------------------------------------------------
__global__ void edge_kernel(const int* __restrict__ ei,     // [2, E]
                            const int* __restrict__ d0r1,   // d0_index row 1, [2E]
                            float* __restrict__ out,
                            int N, int E)
{
    const int warp = (blockIdx.x * blockDim.x + threadIdx.x) >> 5;
    const int lane = threadIdx.x & 31;
    if (warp >= E) return;

    const int s = ei[warp];
    const int d = ei[E + warp];

    const uint2* rs = reinterpret_cast<const uint2*>(g_qk + (size_t)s * QKW);
    const uint2* rd = reinterpret_cast<const uint2*>(g_qk + (size_t)d * QKW);
    // q halves: uint2 indices [0,32), k halves: [32,64)

    uint2 vqs = rs[lane];
    uint2 vks = rs[32 + lane];
    uint2 vqd = rd[lane];
    uint2 vkd = rd[32 + lane];

    __half2 qs0 = *reinterpret_cast<const __half2*>(&vqs.x);
    __half2 qs1 = *reinterpret_cast<const __half2*>(&vqs.y);
    __half2 ks0 = *reinterpret_cast<const __half2*>(&vks.x);
    __half2 ks1 = *reinterpret_cast<const __half2*>(&vks.y);
    __half2 qd0 = *reinterpret_cast<const __half2*>(&vqd.x);
    __half2 qd1 = *reinterpret_cast<const __half2*>(&vqd.y);
    __half2 kd0 = *reinterpret_cast<const __half2*>(&vkd.x);
    __half2 kd1 = *reinterpret_cast<const __half2*>(&vkd.y);

    float2 a, b;
    float p = 0.f;
    a = __half22float2(qs0); b = __half22float2(kd0); p += a.x * b.x + a.y * b.y;
    a = __half22float2(qs1); b = __half22float2(kd1); p += a.x * b.x + a.y * b.y;
    a = __half22float2(qd0); b = __half22float2(ks0); p += a.x * b.x + a.y * b.y;
    a = __half22float2(qd1); b = __half22float2(ks1); p += a.x * b.x + a.y * b.y;

    // butterfly reduce -> every lane holds the full sum
    #pragma unroll
    for (int o = 16; o > 0; o >>= 1)
        p += __shfl_xor_sync(0xffffffffu, p, o);

    const float v = expf(p * 0.0625f);   // 0.5/8 * sum

    if (lane == 0) {
        out[N + warp] = v;                               // diagA1
        atomicAdd(out + d0r1[2 * warp], v);              // diagA0 scatter
    } else if (lane == 1) {
        atomicAdd(out + d0r1[2 * warp + 1], v);
    }
}

// ---------------------------------------------------------------------------
extern "C" void kernel_launch(void* const* d_in, const int* in_sizes, int n_in,
                              void* d_out, int out_size)
{
    const float* x  = (const float*)d_in[0];
    const float* Wq = (const float*)d_in[1];
    const float* bq = (const float*)d_in[2];
    const float* Wk = (const float*)d_in[3];
    const float* bk = (const float*)d_in[4];
    const int*   ei = (const int*)d_in[5];
    const int*   d0 = (const int*)d_in[6];
    float* out = (float*)d_out;

    const int A  = in_sizes[2];              // 128
    const int Dd = in_sizes[1] / A;          // 256
    const int N  = in_sizes[0] / Dd;         // 50000
    const int E  = in_sizes[5] / 2;          // 800000
    const int twoE = in_sizes[6] / 2;        // 2E (row stride of d0_index)
    (void)n_in; (void)out_size;

    // diagA0 accumulators start at zero
    cudaMemsetAsync(out, 0, (size_t)N * sizeof(float), 0);

    // projection GEMM
    dim3 gblk(256);
    dim3 ggrd((N + 63) / 64, QKW / 64);
    gemm_qk_kernel<<<ggrd, gblk>>>(x, Wq, bq, Wk, bk, N);

    // per-edge score + scatter (one warp per edge, 8 warps per block)
    int blocks = (E + 7) / 8;
    edge_kernel<<<blocks, 256>>>(ei, d0 + twoE, out, N, E);
}

// round 3
// speedup vs baseline: 1.9093x; 1.9093x over previous
#include <cuda_runtime.h>
#include <cuda_fp16.h>
#include <mma.h>

using namespace nvcuda;

#define NODES_MAX 50000
#define DDIM 256          // input feature dim
#define ADIM 128          // attention dim (q or k width)
#define QKW 256           // concat width: [q | k]

// fp16 q|k table, one 256-half row per node (25.6 MB static scratch)
__device__ __half g_qk[(size_t)NODES_MAX * QKW];

// ---------------------------------------------------------------------------
// Kernel 1: fused projection GEMM on tensor cores (wmma fp16 -> fp32 accum)
//   qk[n][j] = sum_d x[n][d] * W[j][d] + b[j],  W = [Wq ; Wk]
// BM=128, BN=128, BK=32, 256 threads (8 warps, 2m x 4n), warp tile 64x32.
// x is fp32 in gmem; converted to fp16 while staging into smem.
// ---------------------------------------------------------------------------
__global__ __launch_bounds__(256)
void gemm_qk_wmma(const float* __restrict__ x,
                  const float* __restrict__ Wq,
                  const float* __restrict__ bq,
                  const float* __restrict__ Wk,
                  const float* __restrict__ bk,
                  int N)
{
    __shared__ __half Xs[128][40];    // [m][k], pad 40 to dodge conflicts
    __shared__ __half Bs[128][40];    // [n][k]  (col-major B for wmma)
    __shared__ float  epi[8][256];    // per-warp 16x16 epilogue staging

    const int tid  = threadIdx.x;
    const int wid  = tid >> 5;
    const int lane = tid & 31;
    const int m0   = blockIdx.x * 128;
    const int n0   = blockIdx.y * 128;

    const int wm = wid & 1;           // 0..1 -> m offset wm*64
    const int wn = wid >> 1;          // 0..3 -> n offset wn*32

    wmma::fragment<wmma::accumulator, 16, 16, 16, float> c[4][2];
    #pragma unroll
    for (int i = 0; i < 4; i++)
        #pragma unroll
        for (int j = 0; j < 2; j++)
            wmma::fill_fragment(c[i][j], 0.0f);

    // staging map: 4 iters, each thread one float4
    const int srow = tid >> 3;        // 0..31 (+ i*32)
    const int scol = (tid & 7) * 4;   // 0,4,...,28

    for (int k0 = 0; k0 < DDIM; k0 += 32) {
        #pragma unroll
        for (int i = 0; i < 4; i++) {
            int row = srow + i * 32;
            // A tile
            int gm = m0 + row;
            float4 xv = make_float4(0.f, 0.f, 0.f, 0.f);
            if (gm < N)
                xv = *reinterpret_cast<const float4*>(x + (size_t)gm * DDIM + k0 + scol);
            Xs[row][scol + 0] = __float2half(xv.x);
            Xs[row][scol + 1] = __float2half(xv.y);
            Xs[row][scol + 2] = __float2half(xv.z);
            Xs[row][scol + 3] = __float2half(xv.w);
            // B tile (Wq rows 0..127, Wk rows 128..255)
            int gj = n0 + row;
            const float* wrow = (gj < ADIM) ? (Wq + (size_t)gj * DDIM)
                                            : (Wk + (size_t)(gj - ADIM) * DDIM);
            float4 wv = *reinterpret_cast<const float4*>(wrow + k0 + scol);
            Bs[row][scol + 0] = __float2half(wv.x);
            Bs[row][scol + 1] = __float2half(wv.y);
            Bs[row][scol + 2] = __float2half(wv.z);
            Bs[row][scol + 3] = __float2half(wv.w);
        }
        __syncthreads();

        #pragma unroll
        for (int ks = 0; ks < 32; ks += 16) {
            wmma::fragment<wmma::matrix_a, 16, 16, 16, __half, wmma::row_major> a[4];
            wmma::fragment<wmma::matrix_b, 16, 16, 16, __half, wmma::col_major> b[2];
            #pragma unroll
            for (int i = 0; i < 4; i++)
                wmma::load_matrix_sync(a[i], &Xs[wm * 64 + i * 16][ks], 40);
            #pragma unroll
            for (int j = 0; j < 2; j++)
                wmma::load_matrix_sync(b[j], &Bs[wn * 32 + j * 16][ks], 40);
            #pragma unroll
            for (int i = 0; i < 4; i++)
                #pragma unroll
                for (int j = 0; j < 2; j++)
                    wmma::mma_sync(c[i][j], a[i], b[j], c[i][j]);
        }
        __syncthreads();
    }

    // epilogue: per warp, stage each 16x16 frag to smem, bias-add, fp16 store
    const int erow = lane & 15;           // 0..15
    const int ecg  = (lane >> 4) * 8;     // 0 or 8
    #pragma unroll
    for (int i = 0; i < 4; i++) {
        #pragma unroll
        for (int j = 0; j < 2; j++) {
            wmma::store_matrix_sync(&epi[wid][0], c[i][j], 16, wmma::mem_row_major);
            __syncwarp();
            int gm = m0 + wm * 64 + i * 16 + erow;
            int gj0 = n0 + wn * 32 + j * 16 + ecg;
            if (gm < N) {
                __half hv[8];
                #pragma unroll
                for (int t = 0; t < 8; t++) {
                    int gj = gj0 + t;
                    float bias = (gj < ADIM) ? bq[gj] : bk[gj - ADIM];
                    hv[t] = __float2half(epi[wid][erow * 16 + ecg + t] + bias);
                }
                *reinterpret_cast<uint4*>(g_qk + (size_t)gm * QKW + gj0) =
                    *reinterpret_cast<const uint4*>(hv);
            }
            __syncwarp();
        }
    }
}

// ---------------------------------------------------------------------------
// Kernel 2: per-edge symmetric attention score + fused scatter-add.
// One warp per edge. Row of node n in g_qk: [q(128h) | k(128h)] = 512B = 32 uint4.
// Lanes 0..15 load (q_s chunk, k_d chunk); lanes 16..31 load (q_d chunk, k_s chunk).
// Sum over all lanes = q_s.k_d + q_d.k_s.
// ---------------------------------------------------------------------------
__global__ __launch_bounds__(256)
void edge_kernel(const int* __restrict__ ei,     // [2, E]
                 const int* __restrict__ d0r1,   // d0_index row 1, [2E]
                 float* __restrict__ out,
                 int N, int E)
{
    const int e    = (blockIdx.x * blockDim.x + threadIdx.x) >> 5;
    const int lane = threadIdx.x & 31;
    if (e >= E) return;

    const int s = __ldg(ei + e);
    const int d = __ldg(ei + E + e);

    const uint4* rs = reinterpret_cast<const uint4*>(g_qk + (size_t)s * QKW);
    const uint4* rd = reinterpret_cast<const uint4*>(g_qk + (size_t)d * QKW);

    const bool lo = lane < 16;
    const uint4* pa = lo ? (rs + lane)      : (rd + (lane - 16)); // q_s | q_d
    const uint4* pb = lo ? (rd + 16 + lane) : (rs + lane);        // k_d | k_s
    const uint4 av = *pa;
    const uint4 bv = *pb;

    const __half2* ah = reinterpret_cast<const __half2*>(&av);
    const __half2* bh = reinterpret_cast<const __half2*>(&bv);
    float p = 0.f;
    #pragma unroll
    for (int i = 0; i < 4; i++) {
        float2 fa = __half22float2(ah[i]);
        float2 fb = __half22float2(bh[i]);
        p = fmaf(fa.x, fb.x, p);
        p = fmaf(fa.y, fb.y, p);
    }

    #pragma unroll
    for (int o = 16; o > 0; o >>= 1)
        p += __shfl_xor_sync(0xffffffffu, p, o);

    if (lane == 0) {
        const float v = __expf(p * 0.0625f);   // (0.5/8) * sum
        out[N + e] = v;                        // diagA1
        int2 dp = *reinterpret_cast<const int2*>(d0r1 + 2 * e);
        atomicAdd(out + dp.x, v);              // diagA0 scatter (no return -> RED)
        atomicAdd(out + dp.y, v);
    }
}

// ---------------------------------------------------------------------------
extern "C" void kernel_launch(void* const* d_in, const int* in_sizes, int n_in,
                              void* d_out, int out_size)
{
    const float* x  = (const float*)d_in[0];
    const float* Wq = (const float*)d_in[1];
    const float* bq = (const float*)d_in[2];
    const float* Wk = (const float*)d_in[3];
    const float* bk = (const float*)d_in[4];
    const int*   ei = (const int*)d_in[5];
    const int*   d0 = (const int*)d_in[6];
    float* out = (float*)d_out;

    const int A    = in_sizes[2];             // 128
    const int Dd   = in_sizes[1] / A;         // 256
    const int N    = in_sizes[0] / Dd;        // 50000
    const int E    = in_sizes[5] / 2;         // 800000
    const int twoE = in_sizes[6] / 2;         // 2E (row stride of d0_index)
    (void)n_in; (void)out_size;

    cudaMemsetAsync(out, 0, (size_t)N * sizeof(float), 0);

    dim3 ggrd((N + 127) / 128, QKW / 128);
    gemm_qk_wmma<<<ggrd, 256>>>(x, Wq, bq, Wk, bk, N);

    int blocks = (E + 7) / 8;   // one warp per edge, 8 warps per block
    edge_kernel<<<blocks, 256>>>(ei, d0 + twoE, out, N, E);
}

// round 4
// speedup vs baseline: 2.8490x; 1.4922x over previous
#include <cuda_runtime.h>
#include <cuda_fp16.h>
#include <mma.h>

using namespace nvcuda;

#define NODES_MAX 50000
#define DDIM 256          // input feature dim
#define ADIM 128          // attention dim (q or k width)
#define QKW 256           // concat width: [q | k]

// fp16 q|k table, one 256-half row per node (25.6 MB static scratch)
__device__ __half g_qk[(size_t)NODES_MAX * QKW];

// ---------------------------------------------------------------------------
// Kernel 1: fused projection GEMM on tensor cores (wmma fp16 -> fp32 accum)
//   qk[n][j] = sum_d x[n][d] * W[j][d] + b[j],  W = [Wq ; Wk]
// BM=128, BN=128, BK=32, 256 threads (8 warps, 2m x 4n), warp tile 64x32.
// K-loop double-buffered through registers (gmem load overlaps mma).
// ---------------------------------------------------------------------------
__global__ __launch_bounds__(256)
void gemm_qk_wmma(const float* __restrict__ x,
                  const float* __restrict__ Wq,
                  const float* __restrict__ bq,
                  const float* __restrict__ Wk,
                  const float* __restrict__ bk,
                  int N)
{
    __shared__ __half Xs[128][40];    // [m][k], pad 40 to dodge conflicts
    __shared__ __half Bs[128][40];    // [n][k]  (col-major B for wmma)
    __shared__ float  epi[8][256];    // per-warp 16x16 epilogue staging

    const int tid  = threadIdx.x;
    const int wid  = tid >> 5;
    const int lane = tid & 31;
    const int m0   = blockIdx.x * 128;
    const int n0   = blockIdx.y * 128;

    const int wm = wid & 1;           // 0..1 -> m offset wm*64
    const int wn = wid >> 1;          // 0..3 -> n offset wn*32

    wmma::fragment<wmma::accumulator, 16, 16, 16, float> c[4][2];
    #pragma unroll
    for (int i = 0; i < 4; i++)
        #pragma unroll
        for (int j = 0; j < 2; j++)
            wmma::fill_fragment(c[i][j], 0.0f);

    // staging map: 4 iters, each thread one float4 per tile
    const int srow = tid >> 3;        // 0..31 (+ i*32)
    const int scol = (tid & 7) * 4;   // 0,4,...,28

    const int gm_ld = m0 + srow;      // invariant parts of load addresses
    const float* wrow_base[4];
    #pragma unroll
    for (int i = 0; i < 4; i++) {
        int gj = n0 + srow + i * 32;
        wrow_base[i] = (gj < ADIM) ? (Wq + (size_t)gj * DDIM)
                                   : (Wk + (size_t)(gj - ADIM) * DDIM);
    }

    float4 xr[4], wr[4];
    // prefetch k0 = 0
    #pragma unroll
    for (int i = 0; i < 4; i++) {
        int gm = gm_ld + i * 32;
        xr[i] = make_float4(0.f, 0.f, 0.f, 0.f);
        if (gm < N)
            xr[i] = *reinterpret_cast<const float4*>(x + (size_t)gm * DDIM + scol);
        wr[i] = *reinterpret_cast<const float4*>(wrow_base[i] + scol);
    }

    for (int k0 = 0; k0 < DDIM; k0 += 32) {
        // store prefetched tile to smem
        #pragma unroll
        for (int i = 0; i < 4; i++) {
            int row = srow + i * 32;
            Xs[row][scol + 0] = __float2half(xr[i].x);
            Xs[row][scol + 1] = __float2half(xr[i].y);
            Xs[row][scol + 2] = __float2half(xr[i].z);
            Xs[row][scol + 3] = __float2half(xr[i].w);
            Bs[row][scol + 0] = __float2half(wr[i].x);
            Bs[row][scol + 1] = __float2half(wr[i].y);
            Bs[row][scol + 2] = __float2half(wr[i].z);
            Bs[row][scol + 3] = __float2half(wr[i].w);
        }
        __syncthreads();

        // issue next tile's gmem loads (overlap with mma below)
        const int kn = k0 + 32;
        if (kn < DDIM) {
            #pragma unroll
            for (int i = 0; i < 4; i++) {
                int gm = gm_ld + i * 32;
                xr[i] = make_float4(0.f, 0.f, 0.f, 0.f);
                if (gm < N)
                    xr[i] = *reinterpret_cast<const float4*>(x + (size_t)gm * DDIM + kn + scol);
                wr[i] = *reinterpret_cast<const float4*>(wrow_base[i] + kn + scol);
            }
        }

        #pragma unroll
        for (int ks = 0; ks < 32; ks += 16) {
            wmma::fragment<wmma::matrix_a, 16, 16, 16, __half, wmma::row_major> a[4];
            wmma::fragment<wmma::matrix_b, 16, 16, 16, __half, wmma::col_major> b[2];
            #pragma unroll
            for (int i = 0; i < 4; i++)
                wmma::load_matrix_sync(a[i], &Xs[wm * 64 + i * 16][ks], 40);
            #pragma unroll
            for (int j = 0; j < 2; j++)
                wmma::load_matrix_sync(b[j], &Bs[wn * 32 + j * 16][ks], 40);
            #pragma unroll
            for (int i = 0; i < 4; i++)
                #pragma unroll
                for (int j = 0; j < 2; j++)
                    wmma::mma_sync(c[i][j], a[i], b[j], c[i][j]);
        }
        __syncthreads();
    }

    // epilogue: per warp, stage each 16x16 frag to smem, bias-add, fp16 store
    const int erow = lane & 15;           // 0..15
    const int ecg  = (lane >> 4) * 8;     // 0 or 8
    #pragma unroll
    for (int i = 0; i < 4; i++) {
        #pragma unroll
        for (int j = 0; j < 2; j++) {
            wmma::store_matrix_sync(&epi[wid][0], c[i][j], 16, wmma::mem_row_major);
            __syncwarp();
            int gm = m0 + wm * 64 + i * 16 + erow;
            int gj0 = n0 + wn * 32 + j * 16 + ecg;
            if (gm < N) {
                __half hv[8];
                #pragma unroll
                for (int t = 0; t < 8; t++) {
                    int gj = gj0 + t;
                    float bias = (gj < ADIM) ? bq[gj] : bk[gj - ADIM];
                    hv[t] = __float2half(epi[wid][erow * 16 + ecg + t] + bias);
                }
                *reinterpret_cast<uint4*>(g_qk + (size_t)gm * QKW + gj0) =
                    *reinterpret_cast<const uint4*>(hv);
            }
            __syncwarp();
        }
    }
}

// ---------------------------------------------------------------------------
// Kernel 2: per-edge symmetric attention score + fused scatter-add.
// 8 lanes per edge, 4 edges per warp.
// Row of node n in g_qk: [q(128h) | k(128h)] = 512B = 32 uint4 (q: 0..15, k: 16..31).
// Lane l (0..7) of group g loads 4 independent uint4 pairs covering
//   q_s.k_d (chunks l, l+8) and q_d.k_s (chunks l, l+8)  -> MLP = 8 per lane.
// 3-shuffle butterfly within each 8-lane group; lane l==0 does exp + scatter.
// ---------------------------------------------------------------------------
__global__ __launch_bounds__(256)
void edge_kernel(const int* __restrict__ ei,     // [2, E]
                 const int* __restrict__ d0r1,   // d0_index row 1, [2E]
                 float* __restrict__ out,
                 int N, int E)
{
    const int warp = (blockIdx.x * blockDim.x + threadIdx.x) >> 5;
    const int lane = threadIdx.x & 31;
    const int g    = lane >> 3;          // edge group within warp, 0..3
    const int l    = lane & 7;           // lane within group
    const int e    = warp * 4 + g;
    if (e >= E) return;

    const int s = __ldg(ei + e);
    const int d = __ldg(ei + E + e);

    const uint4* rs = reinterpret_cast<const uint4*>(g_qk + (size_t)s * QKW);
    const uint4* rd = reinterpret_cast<const uint4*>(g_qk + (size_t)d * QKW);

    // 4 independent (a,b) pairs per lane
    const uint4 a0 = rs[l];        const uint4 b0 = rd[16 + l];   // q_s . k_d (lo)
    const uint4 a1 = rs[8 + l];    const uint4 b1 = rd[24 + l];   // q_s . k_d (hi)
    const uint4 a2 = rd[l];        const uint4 b2 = rs[16 + l];   // q_d . k_s (lo)
    const uint4 a3 = rd[8 + l];    const uint4 b3 = rs[24 + l];   // q_d . k_s (hi)

    float p = 0.f;
    {
        const __half2* ah; const __half2* bh;
        #define DOT8(AV, BV)                                         \
            ah = reinterpret_cast<const __half2*>(&(AV));            \
            bh = reinterpret_cast<const __half2*>(&(BV));            \
            _Pragma("unroll")                                        \
            for (int i = 0; i < 4; i++) {                            \
                float2 fa = __half22float2(ah[i]);                   \
                float2 fb = __half22float2(bh[i]);                   \
                p = fmaf(fa.x, fb.x, p);                             \
                p = fmaf(fa.y, fb.y, p);                             \
            }
        DOT8(a0, b0)
        DOT8(a1, b1)
        DOT8(a2, b2)
        DOT8(a3, b3)
        #undef DOT8
    }

    // butterfly within the 8-lane group (offsets 4,2,1 stay inside the group)
    p += __shfl_xor_sync(0xffffffffu, p, 4);
    p += __shfl_xor_sync(0xffffffffu, p, 2);
    p += __shfl_xor_sync(0xffffffffu, p, 1);

    if (l == 0) {
        const float v = __expf(p * 0.0625f);   // (0.5/8) * sum
        out[N + e] = v;                        // diagA1 (4 consecutive e per warp)
        int2 dp = *reinterpret_cast<const int2*>(d0r1 + 2 * e);
        atomicAdd(out + dp.x, v);              // diagA0 scatter (no return -> RED)
        atomicAdd(out + dp.y, v);
    }
}

// ---------------------------------------------------------------------------
extern "C" void kernel_launch(void* const* d_in, const int* in_sizes, int n_in,
                              void* d_out, int out_size)
{
    const float* x  = (const float*)d_in[0];
    const float* Wq = (const float*)d_in[1];
    const float* bq = (const float*)d_in[2];
    const float* Wk = (const float*)d_in[3];
    const float* bk = (const float*)d_in[4];
    const int*   ei = (const int*)d_in[5];
    const int*   d0 = (const int*)d_in[6];
    float* out = (float*)d_out;

    const int A    = in_sizes[2];             // 128
    const int Dd   = in_sizes[1] / A;         // 256
    const int N    = in_sizes[0] / Dd;        // 50000
    const int E    = in_sizes[5] / 2;         // 800000
    const int twoE = in_sizes[6] / 2;         // 2E (row stride of d0_index)
    (void)n_in; (void)out_size;

    cudaMemsetAsync(out, 0, (size_t)N * sizeof(float), 0);

    dim3 ggrd((N + 127) / 128, QKW / 128);
    gemm_qk_wmma<<<ggrd, 256>>>(x, Wq, bq, Wk, bk, N);

    // 4 edges per warp, 8 warps per block
    int nwarps = (E + 3) / 4;
    int blocks = (nwarps + 7) / 8;
    edge_kernel<<<blocks, 256>>>(ei, d0 + twoE, out, N, E);
}

// round 6
// speedup vs baseline: 2.8927x; 1.0153x over previous
#include <cuda_runtime.h>
#include <cuda_fp16.h>
#include <mma.h>
#include <cstdint>

using namespace nvcuda;

#define NODES_MAX 50000
#define DDIM 256          // input feature dim
#define ADIM 128          // attention dim (q or k width)
#define QKW 256           // concat width: [q | k]

// fp16 scratch tables
__device__ __half g_qk[(size_t)NODES_MAX * QKW];   // output of GEMM: [q|k] per node
__device__ __half g_xh[(size_t)NODES_MAX * DDIM];  // fp16 copy of x
__device__ __half g_wh[(size_t)QKW * DDIM];        // fp16 [Wq ; Wk]

// ---------------------------------------------------------------------------
// Kernel 0: fp32 -> fp16 convert for x and W (pure streaming)
// ---------------------------------------------------------------------------
__global__ __launch_bounds__(256)
void convert_kernel(const float* __restrict__ x,
                    const float* __restrict__ Wq,
                    const float* __restrict__ Wk,
                    int nx4, int nw4h)   // nx4 = N*64, nw4h = float4 count of one W
{
    int i = blockIdx.x * blockDim.x + threadIdx.x;
    const int total = nx4 + 2 * nw4h;
    const int stride = gridDim.x * blockDim.x;
    for (; i < total; i += stride) {
        float4 v;
        __half* dst;
        if (i < nx4) {
            v = reinterpret_cast<const float4*>(x)[i];
            dst = g_xh + (size_t)i * 4;
        } else {
            int w = i - nx4;
            v = (w < nw4h) ? reinterpret_cast<const float4*>(Wq)[w]
                           : reinterpret_cast<const float4*>(Wk)[w - nw4h];
            dst = g_wh + (size_t)w * 4;
        }
        __half2 h0 = __floats2half2_rn(v.x, v.y);
        __half2 h1 = __floats2half2_rn(v.z, v.w);
        uint2 pk;
        pk.x = *reinterpret_cast<unsigned int*>(&h0);
        pk.y = *reinterpret_cast<unsigned int*>(&h1);
        *reinterpret_cast<uint2*>(dst) = pk;
    }
}

// ---------------------------------------------------------------------------
// cp.async helpers (16B, L2-cached, zero-fill on predicate false)
// ---------------------------------------------------------------------------
__device__ __forceinline__ void cp16(void* dst, const void* src, bool pred) {
    unsigned sa = (unsigned)__cvta_generic_to_shared(dst);
    int sz = pred ? 16 : 0;
    asm volatile("cp.async.cg.shared.global [%0], [%1], 16, %2;\n"
                 :: "r"(sa), "l"(src), "r"(sz));
}
__device__ __forceinline__ void cp_commit() {
    asm volatile("cp.async.commit_group;\n");
}
template <int W>
__device__ __forceinline__ void cp_wait() {
    asm volatile("cp.async.wait_group %0;\n" :: "n"(W));
}

// ---------------------------------------------------------------------------
// Kernel 1: projection GEMM, fp16 inputs via cp.async 2-stage pipeline.
//   qk[n][j] = sum_d xh[n][d] * wh[j][d] + b[j]
// BM=128, BN=128, BK=32, 256 threads (8 warps, 2m x 4n), warp tile 64x32.
// Static smem: As/Bs 2-stage (40KB); epilogue staging aliases Bs.
// ---------------------------------------------------------------------------
__global__ __launch_bounds__(256)
void gemm_qk_cp(const float* __restrict__ bq,
                const float* __restrict__ bk,
                int N)
{
    __shared__ __align__(16) __half As[2][128][40];   // [stage][m][k], 80B row
    __shared__ __align__(16) __half Bs[2][128][40];   // [stage][n][k]

    const int tid  = threadIdx.x;
    const int wid  = tid >> 5;
    const int lane = tid & 31;
    const int m0   = blockIdx.x * 128;
    const int n0   = blockIdx.y * 128;

    const int wm = wid & 1;           // m offset wm*64
    const int wn = wid >> 1;          // n offset wn*32

    wmma::fragment<wmma::accumulator, 16, 16, 16, float> c[4][2];
    #pragma unroll
    for (int i = 0; i < 4; i++)
        #pragma unroll
        for (int j = 0; j < 2; j++)
            wmma::fill_fragment(c[i][j], 0.0f);

    // load mapping: 512 16B-chunks per tile / 256 thr = 2 chunks/thread (32B)
    const int arow = tid >> 1;              // 0..127
    const int acol = (tid & 1) * 16;        // half offset 0 or 16 (2x16B)
    const int gm   = m0 + arow;
    const bool mok = gm < N;
    const __half* asrc = g_xh + (size_t)gm * DDIM + acol;
    const __half* bsrc = g_wh + (size_t)(n0 + arow) * DDIM + acol;

    // prologue: stages 0 and 1
    #pragma unroll
    for (int s = 0; s < 2; s++) {
        const int k0 = s * 32;
        cp16(&As[s][arow][acol],     asrc + k0,     mok);
        cp16(&As[s][arow][acol + 8], asrc + k0 + 8, mok);
        cp16(&Bs[s][arow][acol],     bsrc + k0,     true);
        cp16(&Bs[s][arow][acol + 8], bsrc + k0 + 8, true);
        cp_commit();
    }

    #pragma unroll
    for (int it = 0; it < DDIM / 32; it++) {
        const int buf = it & 1;
        cp_wait<1>();
        __syncthreads();

        #pragma unroll
        for (int ks = 0; ks < 32; ks += 16) {
            wmma::fragment<wmma::matrix_a, 16, 16, 16, __half, wmma::row_major> a[4];
            wmma::fragment<wmma::matrix_b, 16, 16, 16, __half, wmma::col_major> b[2];
            #pragma unroll
            for (int i = 0; i < 4; i++)
                wmma::load_matrix_sync(a[i], &As[buf][wm * 64 + i * 16][ks], 40);
            #pragma unroll
            for (int j = 0; j < 2; j++)
                wmma::load_matrix_sync(b[j], &Bs[buf][wn * 32 + j * 16][ks], 40);
            #pragma unroll
            for (int i = 0; i < 4; i++)
                #pragma unroll
                for (int j = 0; j < 2; j++)
                    wmma::mma_sync(c[i][j], a[i], b[j], c[i][j]);
        }
        __syncthreads();

        const int kn = (it + 2) * 32;
        if (kn < DDIM) {
            cp16(&As[buf][arow][acol],     asrc + kn,     mok);
            cp16(&As[buf][arow][acol + 8], asrc + kn + 8, mok);
            cp16(&Bs[buf][arow][acol],     bsrc + kn,     true);
            cp16(&Bs[buf][arow][acol + 8], bsrc + kn + 8, true);
            cp_commit();
        }
    }

    // epilogue: alias per-warp f32 staging onto Bs (dead after last barrier)
    float* epw = reinterpret_cast<float*>(&Bs[0][0][0]) + wid * 256;
    const int erow = lane & 15;
    const int ecg  = (lane >> 4) * 8;
    #pragma unroll
    for (int i = 0; i < 4; i++) {
        #pragma unroll
        for (int j = 0; j < 2; j++) {
            wmma::store_matrix_sync(epw, c[i][j], 16, wmma::mem_row_major);
            __syncwarp();
            int gmm = m0 + wm * 64 + i * 16 + erow;
            int gj0 = n0 + wn * 32 + j * 16 + ecg;
            if (gmm < N) {
                __half hv[8];
                #pragma unroll
                for (int t = 0; t < 8; t++) {
                    int gj = gj0 + t;
                    float bias = (gj < ADIM) ? bq[gj] : bk[gj - ADIM];
                    hv[t] = __float2half(epw[erow * 16 + ecg + t] + bias);
                }
                *reinterpret_cast<uint4*>(g_qk + (size_t)gmm * QKW + gj0) =
                    *reinterpret_cast<const uint4*>(hv);
            }
            __syncwarp();
        }
    }
}

// ---------------------------------------------------------------------------
// Kernel 2: per-edge symmetric attention score + fused scatter-add.
// 8 lanes per edge, 4 edges per warp (unchanged from R4).
// ---------------------------------------------------------------------------
__global__ __launch_bounds__(256)
void edge_kernel(const int* __restrict__ ei,     // [2, E]
                 const int* __restrict__ d0r1,   // d0_index row 1, [2E]
                 float* __restrict__ out,
                 int N, int E)
{
    const int warp = (blockIdx.x * blockDim.x + threadIdx.x) >> 5;
    const int lane = threadIdx.x & 31;
    const int g    = lane >> 3;          // edge group within warp, 0..3
    const int l    = lane & 7;           // lane within group
    const int e    = warp * 4 + g;
    if (e >= E) return;

    const int s = __ldg(ei + e);
    const int d = __ldg(ei + E + e);

    const uint4* rs = reinterpret_cast<const uint4*>(g_qk + (size_t)s * QKW);
    const uint4* rd = reinterpret_cast<const uint4*>(g_qk + (size_t)d * QKW);

    const uint4 a0 = rs[l];        const uint4 b0 = rd[16 + l];   // q_s . k_d (lo)
    const uint4 a1 = rs[8 + l];    const uint4 b1 = rd[24 + l];   // q_s . k_d (hi)
    const uint4 a2 = rd[l];        const uint4 b2 = rs[16 + l];   // q_d . k_s (lo)
    const uint4 a3 = rd[8 + l];    const uint4 b3 = rs[24 + l];   // q_d . k_s (hi)

    float p = 0.f;
    {
        const __half2* ah; const __half2* bh;
        #define DOT8(AV, BV)                                         \
            ah = reinterpret_cast<const __half2*>(&(AV));            \
            bh = reinterpret_cast<const __half2*>(&(BV));            \
            _Pragma("unroll")                                        \
            for (int i = 0; i < 4; i++) {                            \
                float2 fa = __half22float2(ah[i]);                   \
                float2 fb = __half22float2(bh[i]);                   \
                p = fmaf(fa.x, fb.x, p);                             \
                p = fmaf(fa.y, fb.y, p);                             \
            }
        DOT8(a0, b0)
        DOT8(a1, b1)
        DOT8(a2, b2)
        DOT8(a3, b3)
        #undef DOT8
    }

    p += __shfl_xor_sync(0xffffffffu, p, 4);
    p += __shfl_xor_sync(0xffffffffu, p, 2);
    p += __shfl_xor_sync(0xffffffffu, p, 1);

    if (l == 0) {
        const float v = __expf(p * 0.0625f);   // (0.5/8) * sum
        out[N + e] = v;                        // diagA1
        int2 dp = *reinterpret_cast<const int2*>(d0r1 + 2 * e);
        atomicAdd(out + dp.x, v);              // diagA0 scatter (no return -> RED)
        atomicAdd(out + dp.y, v);
    }
}

// ---------------------------------------------------------------------------
extern "C" void kernel_launch(void* const* d_in, const int* in_sizes, int n_in,
                              void* d_out, int out_size)
{
    const float* x  = (const float*)d_in[0];
    const float* Wq = (const float*)d_in[1];
    const float* bq = (const float*)d_in[2];
    const float* Wk = (const float*)d_in[3];
    const float* bk = (const float*)d_in[4];
    const int*   ei = (const int*)d_in[5];
    const int*   d0 = (const int*)d_in[6];
    float* out = (float*)d_out;

    const int A    = in_sizes[2];             // 128
    const int Dd   = in_sizes[1] / A;         // 256
    const int N    = in_sizes[0] / Dd;        // 50000
    const int E    = in_sizes[5] / 2;         // 800000
    const int twoE = in_sizes[6] / 2;         // 2E (row stride of d0_index)
    (void)n_in; (void)out_size;

    cudaMemsetAsync(out, 0, (size_t)N * sizeof(float), 0);

    // fp32 -> fp16 tables
    const int nx4  = N * (Dd / 4);
    const int nw4h = A * Dd / 4;
    int cblocks = (nx4 + 2 * nw4h + 255) / 256;
    if (cblocks > 4096) cblocks = 4096;
    convert_kernel<<<cblocks, 256>>>(x, Wq, Wk, nx4, nw4h);

    // projection GEMM
    dim3 ggrd((N + 127) / 128, QKW / 128);
    gemm_qk_cp<<<ggrd, 256>>>(bq, bk, N);

    // per-edge score + scatter: 4 edges per warp, 8 warps per block
    int nwarps = (E + 3) / 4;
    int blocks = (nwarps + 7) / 8;
    edge_kernel<<<blocks, 256>>>(ei, d0 + twoE, out, N, E);
}